// round 10
// baseline (speedup 1.0000x reference)
#include <cuda_runtime.h>
#include <cuda_bf16.h>
#include <math.h>

#define BB 4096
#define TT 200
#define DD 64
#define H1 80
#define H2 40
#define NEG_BIG_F (-4294967295.0f)
#define S1S 84
#define MTOT 208           // tokens padded to 13 m16 tiles

typedef unsigned long long u64;
typedef unsigned int u32;

// A rows: 72 bf16 = 144B (9x16B -> conflict-free ldmatrix)
#define ASTRB 144
// B rows: 88 bf16 = 176B (11x16B -> conflict-free ldmatrix)
#define BSTRB 176

// ---------------- packed fp32x2 (GEMM2) ----------------
__device__ __forceinline__ u64 pack2(float lo, float hi) {
    u64 r; asm("mov.b64 %0, {%1, %2};" : "=l"(r) : "f"(lo), "f"(hi)); return r;
}
__device__ __forceinline__ void unpack2(u64 v, float& lo, float& hi) {
    asm("mov.b64 {%0, %1}, %2;" : "=f"(lo), "=f"(hi) : "l"(v));
}
__device__ __forceinline__ void fma2(u64& d, u64 a, u64 b) {
    asm("fma.rn.f32x2 %0, %1, %2, %0;" : "+l"(d) : "l"(a), "l"(b));
}

__device__ __forceinline__ u32 smem_u32(const void* p) {
    u32 a; asm("{ .reg .u64 t; cvta.to.shared.u64 t, %1; cvt.u32.u64 %0, t; }" : "=r"(a) : "l"(p));
    return a;
}

__device__ __forceinline__ void ldmA(u32& a0, u32& a1, u32& a2, u32& a3, u32 addr) {
    asm volatile("ldmatrix.sync.aligned.m8n8.x4.shared.b16 {%0,%1,%2,%3}, [%4];"
                 : "=r"(a0), "=r"(a1), "=r"(a2), "=r"(a3) : "r"(addr));
}
__device__ __forceinline__ void ldmB(u32& b0, u32& b1, u32 addr) {
    asm volatile("ldmatrix.sync.aligned.m8n8.x2.trans.shared.b16 {%0,%1}, [%2];"
                 : "=r"(b0), "=r"(b1) : "r"(addr));
}
__device__ __forceinline__ void mma_bf16(float* d, u32 a0, u32 a1, u32 a2, u32 a3, u32 b0, u32 b1) {
    asm volatile("mma.sync.aligned.m16n8k16.row.col.f32.bf16.bf16.f32 "
                 "{%0,%1,%2,%3}, {%4,%5,%6,%7}, {%8,%9}, {%0,%1,%2,%3};"
                 : "+f"(d[0]), "+f"(d[1]), "+f"(d[2]), "+f"(d[3])
                 : "r"(a0), "r"(a1), "r"(a2), "r"(a3), "r"(b0), "r"(b1));
}

// ---------------- smem layout (float offsets) ----------------
#define OFF_AH   0                         // 208 x 144B = 29952B = 7488 floats
#define OFF_AL   7488
#define OFF_BH   14976                     // 64 x 176B = 11264B = 2816 floats
#define OFF_BL   17792
#define OFF_C    20608                     // [80]
#define OFF_W2   20688                     // [3200]
#define OFF_B2   23888                     // [40]
#define OFF_WF   23928                     // [40]
#define OFF_QQ   23968                     // [64]
#define OFF_S1   24032                     // [208*84]
#define OFF_P2   41504                     // [1000]
#define OFF_SC   42504                     // [200]
#define OFF_RED  42704                     // [16]
#define OFF_PART 42720                     // [512]
#define OFF_MX   43232                     // [2]
#define SMEM_FLOATS 43236

__device__ __forceinline__ unsigned short bfu(__nv_bfloat16 h) { return __bfloat16_as_ushort(h); }

__global__ __launch_bounds__(512, 1)
void din_attn_kernel(const float* __restrict__ q, const float* __restrict__ kin,
                     const float* __restrict__ v, const int* __restrict__ mask,
                     const float* __restrict__ W1, const float* __restrict__ b1,
                     const float* __restrict__ W2, const float* __restrict__ b2,
                     const float* __restrict__ Wf, const float* __restrict__ bf,
                     float* __restrict__ out)
{
    extern __shared__ float sm[];
    const int tid = threadIdx.x;
    const int wid = tid >> 5;
    const int lid = tid & 31;
    const int b   = blockIdx.x;
    const u32 smb = smem_u32(sm);

    if (tid < DD) sm[OFF_QQ + tid] = q[b * DD + tid];
    __syncthreads();

    // ---- fold W1 -> B (k x n) bf16 hi/lo, rows=i(k), 176B stride ----
    {
        char* bhp = (char*)sm + (size_t)OFF_BH * 4;
        char* blp = (char*)sm + (size_t)OFF_BL * 4;
        for (int idx = tid; idx < DD * H1; idx += 512) {
            int i = idx / H1;
            int j = idx - i * H1;
            float w = W1[(64 + i) * H1 + j] - W1[(128 + i) * H1 + j]
                    + sm[OFF_QQ + i] * W1[(192 + i) * H1 + j];
            __nv_bfloat16 h = __float2bfloat16_rn(w);
            __nv_bfloat16 l = __float2bfloat16_rn(w - __bfloat162float(h));
            size_t o = (size_t)i * BSTRB + (size_t)j * 2;
            *(unsigned short*)(bhp + o) = bfu(h);
            *(unsigned short*)(blp + o) = bfu(l);
        }
    }

    // ---- K -> A (m x k) bf16 hi/lo, rows=token, 144B stride; pad rows 200-207 = 0 ----
    {
        char* ahp = (char*)sm + (size_t)OFF_AH * 4;
        char* alp = (char*)sm + (size_t)OFF_AL * 4;
        for (int idx = tid; idx < MTOT * 16; idx += 512) {
            int t  = idx >> 4;
            int ch = idx & 15;
            uint2 hv = make_uint2(0u, 0u), lv = make_uint2(0u, 0u);
            if (t < TT) {
                float4 kv = *(const float4*)(kin + ((size_t)b * TT + t) * DD + ch * 4);
                __nv_bfloat16 h0 = __float2bfloat16_rn(kv.x);
                __nv_bfloat16 h1 = __float2bfloat16_rn(kv.y);
                __nv_bfloat16 h2 = __float2bfloat16_rn(kv.z);
                __nv_bfloat16 h3 = __float2bfloat16_rn(kv.w);
                __nv_bfloat16 l0 = __float2bfloat16_rn(kv.x - __bfloat162float(h0));
                __nv_bfloat16 l1 = __float2bfloat16_rn(kv.y - __bfloat162float(h1));
                __nv_bfloat16 l2 = __float2bfloat16_rn(kv.z - __bfloat162float(h2));
                __nv_bfloat16 l3 = __float2bfloat16_rn(kv.w - __bfloat162float(h3));
                hv = make_uint2((u32)bfu(h0) | ((u32)bfu(h1) << 16), (u32)bfu(h2) | ((u32)bfu(h3) << 16));
                lv = make_uint2((u32)bfu(l0) | ((u32)bfu(l1) << 16), (u32)bfu(l2) | ((u32)bfu(l3) << 16));
            }
            size_t o = (size_t)t * ASTRB + (size_t)ch * 8;
            *(uint2*)(ahp + o) = hv;
            *(uint2*)(alp + o) = lv;
        }
    }

    // ---- W2 / b2 / Wf / c ----
    for (int idx = tid; idx < H1 * H2; idx += 512) sm[OFF_W2 + idx] = W2[idx];
    if (tid < H2) { sm[OFF_B2 + tid] = b2[tid]; sm[OFF_WF + tid] = Wf[tid]; }
    if (tid < H1) {
        float acc = b1[tid];
        #pragma unroll 8
        for (int i = 0; i < DD; i++)
            acc += sm[OFF_QQ + i] * (W1[i * H1 + tid] + W1[(128 + i) * H1 + tid]);
        sm[OFF_C + tid] = acc;
    }
    __syncthreads();

    // ---- GEMM1 via HMMA: warp w handles m-tile w (13 tiles) ----
    if (wid < 13) {
        const int m0 = wid * 16;
        const u32 aRowH = smb + OFF_AH * 4 + (m0 + (lid & 15)) * ASTRB + (lid >> 4) * 16;
        const u32 aRowL = smb + OFF_AL * 4 + (m0 + (lid & 15)) * ASTRB + (lid >> 4) * 16;
        const u32 bRowH = smb + OFF_BH * 4 + (lid & 15) * BSTRB;
        const u32 bRowL = smb + OFF_BL * 4 + (lid & 15) * BSTRB;

        float acc[10][4];
        #pragma unroll
        for (int n = 0; n < 10; n++) {
            acc[n][0] = 0.f; acc[n][1] = 0.f; acc[n][2] = 0.f; acc[n][3] = 0.f;
        }

        #pragma unroll
        for (int k = 0; k < 4; k++) {
            u32 ah0, ah1, ah2, ah3, al0, al1, al2, al3;
            ldmA(ah0, ah1, ah2, ah3, aRowH + k * 32);
            ldmA(al0, al1, al2, al3, aRowL + k * 32);
            #pragma unroll
            for (int n = 0; n < 10; n++) {
                u32 bh0, bh1, bl0, bl1;
                ldmB(bh0, bh1, bRowH + k * 16 * BSTRB + n * 16);
                ldmB(bl0, bl1, bRowL + k * 16 * BSTRB + n * 16);
                mma_bf16(acc[n], ah0, ah1, ah2, ah3, bh0, bh1);  // Ah*Bh
                mma_bf16(acc[n], al0, al1, al2, al3, bh0, bh1);  // Al*Bh
                mma_bf16(acc[n], ah0, ah1, ah2, ah3, bl0, bl1);  // Ah*Bl
            }
        }

        // epilogue: add bias c, relu, store S1 fp32
        const int r0 = m0 + (lid >> 2);
        #pragma unroll
        for (int n = 0; n < 10; n++) {
            const int jc = n * 8 + (lid & 3) * 2;
            const float c0 = sm[OFF_C + jc];
            const float c1 = sm[OFF_C + jc + 1];
            *(float2*)(sm + OFF_S1 + (size_t)r0 * S1S + jc) =
                make_float2(fmaxf(acc[n][0] + c0, 0.f), fmaxf(acc[n][1] + c1, 0.f));
            *(float2*)(sm + OFF_S1 + (size_t)(r0 + 8) * S1S + jc) =
                make_float2(fmaxf(acc[n][2] + c0, 0.f), fmaxf(acc[n][3] + c1, 0.f));
        }
    }
    __syncthreads();

    // ---- GEMM2: 8tok x 8g tiles, 2-way j-split (500 threads) ----
    float* pbuf = sm + OFF_AH;   // A region free now; 125*64 floats
    const int tile2 = tid >> 1;
    const int half  = tid & 1;
    u64 acc[8][4];
    if (tid < 250) {
        const int tg2 = tile2 / 5;
        const int gg  = tile2 - tg2 * 5;
        const int gc  = gg * 8;
        const int j0  = half * 40;
        const float* s1b = sm + OFF_S1 + (size_t)(tg2 * 8) * S1S;
        const float* w2s = sm + OFF_W2;

        if (half == 0) {
            u64 c0 = pack2(sm[OFF_B2+gc],   sm[OFF_B2+gc+1]);
            u64 c1 = pack2(sm[OFF_B2+gc+2], sm[OFF_B2+gc+3]);
            u64 c2 = pack2(sm[OFF_B2+gc+4], sm[OFF_B2+gc+5]);
            u64 c3 = pack2(sm[OFF_B2+gc+6], sm[OFF_B2+gc+7]);
            #pragma unroll
            for (int tt = 0; tt < 8; tt++) { acc[tt][0]=c0; acc[tt][1]=c1; acc[tt][2]=c2; acc[tt][3]=c3; }
        } else {
            #pragma unroll
            for (int tt = 0; tt < 8; tt++) { acc[tt][0]=0; acc[tt][1]=0; acc[tt][2]=0; acc[tt][3]=0; }
        }

        #pragma unroll 2
        for (int j = j0; j < j0 + 40; j += 4) {
            float sr[8][4];
            #pragma unroll
            for (int tt = 0; tt < 8; tt++)
                *(float4*)sr[tt] = *(const float4*)(s1b + tt * S1S + j);
            #pragma unroll
            for (int ji = 0; ji < 4; ji++) {
                const ulonglong2* wr = (const ulonglong2*)(w2s + (j + ji) * H2 + gc);
                ulonglong2 wA = wr[0];
                ulonglong2 wB = wr[1];
                #pragma unroll
                for (int tt = 0; tt < 8; tt++) {
                    u64 s = pack2(sr[tt][ji], sr[tt][ji]);
                    fma2(acc[tt][0], s, wA.x);
                    fma2(acc[tt][1], s, wA.y);
                    fma2(acc[tt][2], s, wB.x);
                    fma2(acc[tt][3], s, wB.y);
                }
            }
        }
        if (half == 1) {
            u64* dst = (u64*)(pbuf + (size_t)tile2 * 64);
            #pragma unroll
            for (int tt = 0; tt < 8; tt++) {
                dst[tt*4+0] = acc[tt][0]; dst[tt*4+1] = acc[tt][1];
                dst[tt*4+2] = acc[tt][2]; dst[tt*4+3] = acc[tt][3];
            }
        }
    }
    __syncthreads();

    if (tid < 250 && half == 0) {
        const int tg2 = tile2 / 5;
        const int gg  = tile2 - tg2 * 5;
        const int gc  = gg * 8;
        const u64* src = (const u64*)(pbuf + (size_t)tile2 * 64);
        const float* wfp = sm + OFF_WF + gc;
        #pragma unroll
        for (int tt = 0; tt < 8; tt++) {
            float s = 0.f;
            #pragma unroll
            for (int g4 = 0; g4 < 4; g4++) {
                float a0, a1, p0, p1;
                unpack2(acc[tt][g4], a0, a1);
                unpack2(src[tt*4+g4], p0, p1);
                s = fmaf(fmaxf(a0 + p0, 0.f), wfp[2*g4],   s);
                s = fmaf(fmaxf(a1 + p1, 0.f), wfp[2*g4+1], s);
            }
            sm[OFF_P2 + (tg2 * 8 + tt) * 5 + gg] = s;
        }
    }
    __syncthreads();

    // ---- score assembly + mask ----
    if (tid < TT) {
        const float* p2 = sm + OFF_P2 + tid * 5;
        float s = bf[0] + ((p2[0] + p2[1]) + (p2[2] + p2[3]) + p2[4]);
        if (mask[(size_t)b * TT + tid] == 0) s = NEG_BIG_F;
        sm[OFF_SC + tid] = s;
    }
    __syncthreads();

    // ---- softmax over T (16 warps) ----
    float mval = (tid < TT) ? sm[OFF_SC + tid] : -3.0e38f;
    #pragma unroll
    for (int o = 16; o; o >>= 1)
        mval = fmaxf(mval, __shfl_xor_sync(0xffffffffu, mval, o));
    if (lid == 0) sm[OFF_RED + wid] = mval;
    __syncthreads();
    if (tid == 0) {
        float m = sm[OFF_RED];
        #pragma unroll
        for (int w = 1; w < 16; w++) m = fmaxf(m, sm[OFF_RED + w]);
        sm[OFF_MX] = m;
    }
    __syncthreads();
    const float mx = sm[OFF_MX];
    float e = (tid < TT) ? __expf(sm[OFF_SC + tid] - mx) : 0.0f;
    if (tid < TT) sm[OFF_SC + tid] = e;
    float sval = e;
    #pragma unroll
    for (int o = 16; o; o >>= 1)
        sval += __shfl_xor_sync(0xffffffffu, sval, o);
    if (lid == 0) sm[OFF_RED + wid] = sval;
    __syncthreads();
    if (tid == 0) {
        float smv = 0.0f;
        #pragma unroll
        for (int w = 0; w < 16; w++) smv += sm[OFF_RED + w];
        sm[OFF_MX + 1] = 1.0f / smv;
    }
    __syncthreads();

    // ---- out = attn @ V (8 partial groups of 25 tokens) ----
    const float inv = sm[OFF_MX + 1];
    const int dd = tid & 63;
    const int p  = tid >> 6;
    const float* vb = v + (size_t)b * TT * DD;
    const float* scp = sm + OFF_SC;
    float a0 = 0.f;
    const int t0 = p * 25;
    #pragma unroll 5
    for (int t = t0; t < t0 + 25; t++)
        a0 = fmaf(scp[t], vb[(size_t)t * DD + dd], a0);
    sm[OFF_PART + tid] = a0;
    __syncthreads();
    if (tid < DD) {
        float r = 0.f;
        #pragma unroll
        for (int g = 0; g < 8; g++) r += sm[OFF_PART + tid + 64 * g];
        out[(size_t)b * DD + tid] = r * inv;
    }
}

extern "C" void kernel_launch(void* const* d_in, const int* in_sizes, int n_in,
                              void* d_out, int out_size)
{
    const float* q    = (const float*)d_in[0];
    const float* k    = (const float*)d_in[1];
    const float* v    = (const float*)d_in[2];
    const int*   mask = (const int*)  d_in[3];
    const float* W1   = (const float*)d_in[4];
    const float* b1   = (const float*)d_in[5];
    const float* W2   = (const float*)d_in[6];
    const float* b2   = (const float*)d_in[7];
    const float* Wf   = (const float*)d_in[8];
    const float* bf   = (const float*)d_in[9];
    float* out = (float*)d_out;

    const int smem_bytes = SMEM_FLOATS * (int)sizeof(float);
    cudaFuncSetAttribute(din_attn_kernel,
                         cudaFuncAttributeMaxDynamicSharedMemorySize, smem_bytes);
    din_attn_kernel<<<BB, 512, smem_bytes>>>(q, k, v, mask, W1, b1, W2, b2, Wf, bf, out);
}

// round 11
// speedup vs baseline: 1.8811x; 1.8811x over previous
#include <cuda_runtime.h>
#include <cuda_bf16.h>
#include <math.h>

#define BB 4096
#define TT 200
#define DD 64
#define H1 80
#define H2 40
#define NEG_BIG_F (-4294967295.0f)
#define MTOT 208
#define ASTRB 144   // A rows: 72 bf16 (9x16B, conflict-free ldmatrix)
#define BSTRB 176   // B rows: 88 bf16 (11x16B, conflict-free ldmatrix)
#define W2S 44      // W2^T row stride in floats (176B)

typedef unsigned long long u64;
typedef unsigned int u32;

__device__ __forceinline__ u32 smem_u32(const void* p) {
    u32 a; asm("{ .reg .u64 t; cvta.to.shared.u64 t, %1; cvt.u32.u64 %0, t; }" : "=r"(a) : "l"(p));
    return a;
}
__device__ __forceinline__ void ldmA(u32& a0, u32& a1, u32& a2, u32& a3, u32 addr) {
    asm volatile("ldmatrix.sync.aligned.m8n8.x4.shared.b16 {%0,%1,%2,%3}, [%4];"
                 : "=r"(a0), "=r"(a1), "=r"(a2), "=r"(a3) : "r"(addr));
}
__device__ __forceinline__ void ldmB(u32& b0, u32& b1, u32 addr) {
    asm volatile("ldmatrix.sync.aligned.m8n8.x2.trans.shared.b16 {%0,%1}, [%2];"
                 : "=r"(b0), "=r"(b1) : "r"(addr));
}
__device__ __forceinline__ void mma_bf16(float* d, u32 a0, u32 a1, u32 a2, u32 a3, u32 b0, u32 b1) {
    asm volatile("mma.sync.aligned.m16n8k16.row.col.f32.bf16.bf16.f32 "
                 "{%0,%1,%2,%3}, {%4,%5,%6,%7}, {%8,%9}, {%0,%1,%2,%3};"
                 : "+f"(d[0]), "+f"(d[1]), "+f"(d[2]), "+f"(d[3])
                 : "r"(a0), "r"(a1), "r"(a2), "r"(a3), "r"(b0), "r"(b1));
}
__device__ __forceinline__ unsigned short bfu(__nv_bfloat16 h) { return __bfloat16_as_ushort(h); }

// split fp32 -> (hi, lo) bf16 words packed pairwise
__device__ __forceinline__ void split2(float x0, float x1, u32& hi, u32& lo) {
    __nv_bfloat16 h0 = __float2bfloat16_rn(x0);
    __nv_bfloat16 h1 = __float2bfloat16_rn(x1);
    __nv_bfloat16 l0 = __float2bfloat16_rn(x0 - __bfloat162float(h0));
    __nv_bfloat16 l1 = __float2bfloat16_rn(x1 - __bfloat162float(h1));
    hi = (u32)bfu(h0) | ((u32)bfu(h1) << 16);
    lo = (u32)bfu(l0) | ((u32)bfu(l1) << 16);
}

// ---------------- smem layout (float offsets) ----------------
#define OFF_AH   0            // 208 x 144B
#define OFF_AL   7488
#define OFF_BH   14976        // 64 x 176B
#define OFF_BL   17792
#define OFF_W2H  20608        // W2^T hi: 40 rows x 176B
#define OFF_W2L  22368
#define OFF_C    24128        // [80]
#define OFF_B2   24208        // [40]
#define OFF_WF   24248        // [40]
#define OFF_QQ   24288        // [64]
#define OFF_SC   24352        // [208]
#define OFF_RED  24560        // [8]
#define OFF_PART 24568        // [256]
#define OFF_MX   24824        // [2]
#define SMEM_FLOATS 24826

__global__ __launch_bounds__(256, 2)
void din_attn_kernel(const float* __restrict__ q, const float* __restrict__ kin,
                     const float* __restrict__ v, const int* __restrict__ mask,
                     const float* __restrict__ W1, const float* __restrict__ b1,
                     const float* __restrict__ W2, const float* __restrict__ b2,
                     const float* __restrict__ Wf, const float* __restrict__ bf,
                     float* __restrict__ out)
{
    extern __shared__ float sm[];
    const int tid = threadIdx.x;
    const int wid = tid >> 5;
    const int lid = tid & 31;
    const int b   = blockIdx.x;
    const u32 smb = smem_u32(sm);

    if (tid < DD) sm[OFF_QQ + tid] = q[b * DD + tid];
    __syncthreads();

    // ---- fold W1 -> B (k x n) bf16 hi/lo ----
    {
        char* bhp = (char*)sm + (size_t)OFF_BH * 4;
        char* blp = (char*)sm + (size_t)OFF_BL * 4;
        for (int idx = tid; idx < DD * H1; idx += 256) {
            int i = idx / H1;
            int j = idx - i * H1;
            float w = W1[(64 + i) * H1 + j] - W1[(128 + i) * H1 + j]
                    + sm[OFF_QQ + i] * W1[(192 + i) * H1 + j];
            __nv_bfloat16 h = __float2bfloat16_rn(w);
            __nv_bfloat16 l = __float2bfloat16_rn(w - __bfloat162float(h));
            size_t o = (size_t)i * BSTRB + (size_t)j * 2;
            *(unsigned short*)(bhp + o) = bfu(h);
            *(unsigned short*)(blp + o) = bfu(l);
        }
    }

    // ---- K -> A (m x k) bf16 hi/lo; rows 200-207 zero ----
    {
        char* ahp = (char*)sm + (size_t)OFF_AH * 4;
        char* alp = (char*)sm + (size_t)OFF_AL * 4;
        for (int idx = tid; idx < MTOT * 16; idx += 256) {
            int t  = idx >> 4;
            int ch = idx & 15;
            uint2 hv = make_uint2(0u, 0u), lv = make_uint2(0u, 0u);
            if (t < TT) {
                float4 kv = *(const float4*)(kin + ((size_t)b * TT + t) * DD + ch * 4);
                u32 h0, l0, h1, l1;
                split2(kv.x, kv.y, h0, l0);
                split2(kv.z, kv.w, h1, l1);
                hv = make_uint2(h0, h1);
                lv = make_uint2(l0, l1);
            }
            size_t o = (size_t)t * ASTRB + (size_t)ch * 8;
            *(uint2*)(ahp + o) = hv;
            *(uint2*)(alp + o) = lv;
        }
    }

    // ---- W2^T bf16 hi/lo, b2, Wf, bias c ----
    {
        char* w2h = (char*)sm + (size_t)OFF_W2H * 4;
        char* w2l = (char*)sm + (size_t)OFF_W2L * 4;
        for (int idx = tid; idx < H1 * H2; idx += 256) {
            int j = idx / H2;
            int g = idx - j * H2;
            float w = W2[idx];
            __nv_bfloat16 h = __float2bfloat16_rn(w);
            __nv_bfloat16 l = __float2bfloat16_rn(w - __bfloat162float(h));
            size_t o = (size_t)g * (W2S * 4) + (size_t)j * 2;
            *(unsigned short*)(w2h + o) = bfu(h);
            *(unsigned short*)(w2l + o) = bfu(l);
        }
    }
    if (tid < H2) { sm[OFF_B2 + tid] = b2[tid]; sm[OFF_WF + tid] = Wf[tid]; }
    if (tid < H1) {
        float acc = b1[tid];
        #pragma unroll 8
        for (int i = 0; i < DD; i++)
            acc += sm[OFF_QQ + i] * (W1[i * H1 + tid] + W1[(128 + i) * H1 + tid]);
        sm[OFF_C + tid] = acc;
    }
    __syncthreads();

    // ---- fused GEMM1 (HMMA) -> relu -> GEMM2 (HMMA) -> scores ----
    #pragma unroll 1
    for (int pass = 0; pass < 2; pass++) {
        const int tile = wid + pass * 8;
        if (tile >= 13) break;
        const int m0 = tile * 16;
        const u32 aRowH = smb + OFF_AH * 4 + (m0 + (lid & 15)) * ASTRB + (lid >> 4) * 16;
        const u32 aRowL = smb + OFF_AL * 4 + (m0 + (lid & 15)) * ASTRB + (lid >> 4) * 16;
        const u32 bRowH = smb + OFF_BH * 4 + (lid & 15) * BSTRB;
        const u32 bRowL = smb + OFF_BL * 4 + (lid & 15) * BSTRB;

        float acc[10][4];
        #pragma unroll
        for (int n = 0; n < 10; n++) {
            acc[n][0] = 0.f; acc[n][1] = 0.f; acc[n][2] = 0.f; acc[n][3] = 0.f;
        }
        #pragma unroll
        for (int k = 0; k < 4; k++) {
            u32 ah0, ah1, ah2, ah3, al0, al1, al2, al3;
            ldmA(ah0, ah1, ah2, ah3, aRowH + k * 32);
            ldmA(al0, al1, al2, al3, aRowL + k * 32);
            #pragma unroll
            for (int n = 0; n < 10; n++) {
                u32 bh0, bh1, bl0, bl1;
                ldmB(bh0, bh1, bRowH + k * 16 * BSTRB + n * 16);
                ldmB(bl0, bl1, bRowL + k * 16 * BSTRB + n * 16);
                mma_bf16(acc[n], ah0, ah1, ah2, ah3, bh0, bh1);
                mma_bf16(acc[n], al0, al1, al2, al3, bh0, bh1);
                mma_bf16(acc[n], ah0, ah1, ah2, ah3, bl0, bl1);
            }
        }

        // bias + relu, in-register split to GEMM2 A-frags
        u32 fh[5][4], fl[5][4];   // per k-step: a0..a3 hi and lo
        {
            const int cc = (lid & 3) * 2;
            #pragma unroll
            for (int n = 0; n < 10; n++) {
                const float c0 = sm[OFF_C + n * 8 + cc];
                const float c1 = sm[OFF_C + n * 8 + cc + 1];
                float x0 = fmaxf(acc[n][0] + c0, 0.f);
                float x1 = fmaxf(acc[n][1] + c1, 0.f);
                float x2 = fmaxf(acc[n][2] + c0, 0.f);
                float x3 = fmaxf(acc[n][3] + c1, 0.f);
                const int kk = n >> 1;
                const int hi2 = (n & 1) * 2;     // 0 -> a0/a1 slots, 1 -> a2/a3 slots
                split2(x0, x1, fh[kk][hi2],     fl[kk][hi2]);
                split2(x2, x3, fh[kk][hi2 + 1], fl[kk][hi2 + 1]);
            }
        }

        // GEMM2: acc2[5][4] over 40 cols, k=80 in 5 k16 steps
        float acc2[5][4];
        {
            const int cc = (lid & 3) * 2;
            #pragma unroll
            for (int n2 = 0; n2 < 5; n2++) {
                const float bb0 = sm[OFF_B2 + n2 * 8 + cc];
                const float bb1 = sm[OFF_B2 + n2 * 8 + cc + 1];
                acc2[n2][0] = bb0; acc2[n2][1] = bb1;
                acc2[n2][2] = bb0; acc2[n2][3] = bb1;
            }
        }
        {
            const u32 w2hB = smb + OFF_W2H * 4;
            const u32 w2lB = smb + OFF_W2L * 4;
            const int nrow = (lid >> 2);        // 0..7
            const int kw   = (lid & 3);         // word within k16
            #pragma unroll
            for (int kk = 0; kk < 5; kk++) {
                #pragma unroll
                for (int n2 = 0; n2 < 5; n2++) {
                    const u32 base = (u32)(((n2 * 8 + nrow) * W2S + kk * 8 + kw) * 4);
                    u32 bh0 = *(const u32*)((char*)sm + w2hB - smb + base);
                    u32 bh1 = *(const u32*)((char*)sm + w2hB - smb + base + 16);
                    u32 bl0 = *(const u32*)((char*)sm + w2lB - smb + base);
                    u32 bl1 = *(const u32*)((char*)sm + w2lB - smb + base + 16);
                    mma_bf16(acc2[n2], fh[kk][0], fh[kk][1], fh[kk][2], fh[kk][3], bh0, bh1);
                    mma_bf16(acc2[n2], fl[kk][0], fl[kk][1], fl[kk][2], fl[kk][3], bh0, bh1);
                    mma_bf16(acc2[n2], fh[kk][0], fh[kk][1], fh[kk][2], fh[kk][3], bl0, bl1);
                }
            }
        }

        // scores: relu(acc2) . Wf, reduce over lane quads
        {
            const int cc = (lid & 3) * 2;
            float s0 = 0.f, s1 = 0.f;
            #pragma unroll
            for (int n2 = 0; n2 < 5; n2++) {
                const float w0 = sm[OFF_WF + n2 * 8 + cc];
                const float w1 = sm[OFF_WF + n2 * 8 + cc + 1];
                s0 = fmaf(fmaxf(acc2[n2][0], 0.f), w0, s0);
                s0 = fmaf(fmaxf(acc2[n2][1], 0.f), w1, s0);
                s1 = fmaf(fmaxf(acc2[n2][2], 0.f), w0, s1);
                s1 = fmaf(fmaxf(acc2[n2][3], 0.f), w1, s1);
            }
            s0 += __shfl_xor_sync(0xffffffffu, s0, 1);
            s0 += __shfl_xor_sync(0xffffffffu, s0, 2);
            s1 += __shfl_xor_sync(0xffffffffu, s1, 1);
            s1 += __shfl_xor_sync(0xffffffffu, s1, 2);
            if ((lid & 3) == 0) {
                const int r0 = m0 + (lid >> 2);
                if (r0 < TT)     sm[OFF_SC + r0] = s0;
                if (r0 + 8 < TT) sm[OFF_SC + r0 + 8] = s1;
            }
        }
    }
    __syncthreads();

    // ---- bias + mask ----
    if (tid < TT) {
        float s = sm[OFF_SC + tid] + bf[0];
        if (mask[(size_t)b * TT + tid] == 0) s = NEG_BIG_F;
        sm[OFF_SC + tid] = s;
    }
    __syncthreads();

    // ---- softmax over T (8 warps) ----
    float mval = (tid < TT) ? sm[OFF_SC + tid] : -3.0e38f;
    #pragma unroll
    for (int o = 16; o; o >>= 1)
        mval = fmaxf(mval, __shfl_xor_sync(0xffffffffu, mval, o));
    if (lid == 0) sm[OFF_RED + wid] = mval;
    __syncthreads();
    if (tid == 0) {
        float m = sm[OFF_RED];
        #pragma unroll
        for (int w = 1; w < 8; w++) m = fmaxf(m, sm[OFF_RED + w]);
        sm[OFF_MX] = m;
    }
    __syncthreads();
    const float mx = sm[OFF_MX];
    float e = (tid < TT) ? __expf(sm[OFF_SC + tid] - mx) : 0.0f;
    if (tid < TT) sm[OFF_SC + tid] = e;
    float sval = e;
    #pragma unroll
    for (int o = 16; o; o >>= 1)
        sval += __shfl_xor_sync(0xffffffffu, sval, o);
    if (lid == 0) sm[OFF_RED + wid] = sval;
    __syncthreads();
    if (tid == 0) {
        float smv = 0.0f;
        #pragma unroll
        for (int w = 0; w < 8; w++) smv += sm[OFF_RED + w];
        sm[OFF_MX + 1] = 1.0f / smv;
    }
    __syncthreads();

    // ---- out = attn @ V (4 partial groups of 50 tokens) ----
    const float inv = sm[OFF_MX + 1];
    const int dd = tid & 63;
    const int p  = tid >> 6;
    const float* vb = v + (size_t)b * TT * DD;
    const float* scp = sm + OFF_SC;
    float a0 = 0.f, a1 = 0.f;
    const int t0 = p * 50;
    #pragma unroll 5
    for (int t = t0; t < t0 + 50; t += 2) {
        a0 = fmaf(scp[t],     vb[(size_t)t * DD + dd],       a0);
        a1 = fmaf(scp[t + 1], vb[(size_t)(t + 1) * DD + dd], a1);
    }
    sm[OFF_PART + tid] = a0 + a1;
    __syncthreads();
    if (tid < DD) {
        float r = sm[OFF_PART + tid] + sm[OFF_PART + tid + 64]
                + sm[OFF_PART + tid + 128] + sm[OFF_PART + tid + 192];
        out[(size_t)b * DD + tid] = r * inv;
    }
}

extern "C" void kernel_launch(void* const* d_in, const int* in_sizes, int n_in,
                              void* d_out, int out_size)
{
    const float* q    = (const float*)d_in[0];
    const float* k    = (const float*)d_in[1];
    const float* v    = (const float*)d_in[2];
    const int*   mask = (const int*)  d_in[3];
    const float* W1   = (const float*)d_in[4];
    const float* b1   = (const float*)d_in[5];
    const float* W2   = (const float*)d_in[6];
    const float* b2   = (const float*)d_in[7];
    const float* Wf   = (const float*)d_in[8];
    const float* bf   = (const float*)d_in[9];
    float* out = (float*)d_out;

    const int smem_bytes = SMEM_FLOATS * (int)sizeof(float);
    cudaFuncSetAttribute(din_attn_kernel,
                         cudaFuncAttributeMaxDynamicSharedMemorySize, smem_bytes);
    din_attn_kernel<<<BB, 256, smem_bytes>>>(q, k, v, mask, W1, b1, W2, b2, Wf, bf, out);
}

// round 12
// speedup vs baseline: 1.9123x; 1.0166x over previous
#include <cuda_runtime.h>
#include <cuda_bf16.h>
#include <math.h>

#define BB 4096
#define TT 200
#define DD 64
#define H1 80
#define H2 40
#define NEG_BIG_F (-4294967295.0f)
#define ASTRB 144   // per-warp A rows: 72 bf16 (9x16B, conflict-free ldmatrix)
#define BSTRB 176   // B rows: 88 bf16 (11x16B, conflict-free ldmatrix)
#define W2S 44      // W2^T row stride in floats (176B)
#define AWBYTES 4608  // per-warp A buffer: 16*144 (hi) + 16*144 (lo)

typedef unsigned long long u64;
typedef unsigned int u32;

__device__ __forceinline__ u32 smem_u32(const void* p) {
    u32 a; asm("{ .reg .u64 t; cvta.to.shared.u64 t, %1; cvt.u32.u64 %0, t; }" : "=r"(a) : "l"(p));
    return a;
}
__device__ __forceinline__ void ldmA(u32& a0, u32& a1, u32& a2, u32& a3, u32 addr) {
    asm volatile("ldmatrix.sync.aligned.m8n8.x4.shared.b16 {%0,%1,%2,%3}, [%4];"
                 : "=r"(a0), "=r"(a1), "=r"(a2), "=r"(a3) : "r"(addr));
}
__device__ __forceinline__ void ldmB(u32& b0, u32& b1, u32 addr) {
    asm volatile("ldmatrix.sync.aligned.m8n8.x2.trans.shared.b16 {%0,%1}, [%2];"
                 : "=r"(b0), "=r"(b1) : "r"(addr));
}
__device__ __forceinline__ void mma_bf16(float* d, u32 a0, u32 a1, u32 a2, u32 a3, u32 b0, u32 b1) {
    asm volatile("mma.sync.aligned.m16n8k16.row.col.f32.bf16.bf16.f32 "
                 "{%0,%1,%2,%3}, {%4,%5,%6,%7}, {%8,%9}, {%0,%1,%2,%3};"
                 : "+f"(d[0]), "+f"(d[1]), "+f"(d[2]), "+f"(d[3])
                 : "r"(a0), "r"(a1), "r"(a2), "r"(a3), "r"(b0), "r"(b1));
}
__device__ __forceinline__ unsigned short bfu(__nv_bfloat16 h) { return __bfloat16_as_ushort(h); }

__device__ __forceinline__ void split2(float x0, float x1, u32& hi, u32& lo) {
    __nv_bfloat16 h0 = __float2bfloat16_rn(x0);
    __nv_bfloat16 h1 = __float2bfloat16_rn(x1);
    __nv_bfloat16 l0 = __float2bfloat16_rn(x0 - __bfloat162float(h0));
    __nv_bfloat16 l1 = __float2bfloat16_rn(x1 - __bfloat162float(h1));
    hi = (u32)bfu(h0) | ((u32)bfu(h1) << 16);
    lo = (u32)bfu(l0) | ((u32)bfu(l1) << 16);
}

// ---------------- smem layout (float offsets) ----------------
#define OFF_AW   0            // 8 warps x 4608B = 36864B (aliases CP in fold, PART in AV)
#define OFF_BH   9216
#define OFF_BL   12032
#define OFF_W2H  14848
#define OFF_W2L  16608
#define OFF_C    18368        // [80]
#define OFF_B2   18448        // [40]
#define OFF_WF   18488        // [40]
#define OFF_QQ   18528        // [64]
#define OFF_SC   18592        // [208]
#define OFF_RED  18800        // [8]
#define OFF_MX   18808        // [2]
#define SMEM_FLOATS 18810

__global__ __launch_bounds__(256, 3)
void din_attn_kernel(const float* __restrict__ q, const float* __restrict__ kin,
                     const float* __restrict__ v, const int* __restrict__ mask,
                     const float* __restrict__ W1, const float* __restrict__ b1,
                     const float* __restrict__ W2, const float* __restrict__ b2,
                     const float* __restrict__ Wf, const float* __restrict__ bf,
                     float* __restrict__ out)
{
    extern __shared__ float sm[];
    const int tid = threadIdx.x;
    const int wid = tid >> 5;
    const int lid = tid & 31;
    const int b   = blockIdx.x;
    const u32 smb = smem_u32(sm);

    if (tid < DD) sm[OFF_QQ + tid] = q[b * DD + tid];
    __syncthreads();

    // ---- fold W1 -> B (k x n) bf16 hi/lo ----
    {
        char* bhp = (char*)sm + (size_t)OFF_BH * 4;
        char* blp = (char*)sm + (size_t)OFF_BL * 4;
        for (int idx = tid; idx < DD * H1; idx += 256) {
            int i = idx / H1;
            int j = idx - i * H1;
            float w = W1[(64 + i) * H1 + j] - W1[(128 + i) * H1 + j]
                    + sm[OFF_QQ + i] * W1[(192 + i) * H1 + j];
            __nv_bfloat16 h = __float2bfloat16_rn(w);
            __nv_bfloat16 l = __float2bfloat16_rn(w - __bfloat162float(h));
            size_t o = (size_t)i * BSTRB + (size_t)j * 2;
            *(unsigned short*)(bhp + o) = bfu(h);
            *(unsigned short*)(blp + o) = bfu(l);
        }
    }

    // ---- W2^T bf16 hi/lo ----
    {
        char* w2h = (char*)sm + (size_t)OFF_W2H * 4;
        char* w2l = (char*)sm + (size_t)OFF_W2L * 4;
        for (int idx = tid; idx < H1 * H2; idx += 256) {
            int j = idx / H2;
            int g = idx - j * H2;
            float w = W2[idx];
            __nv_bfloat16 h = __float2bfloat16_rn(w);
            __nv_bfloat16 l = __float2bfloat16_rn(w - __bfloat162float(h));
            size_t o = (size_t)g * (W2S * 4) + (size_t)j * 2;
            *(unsigned short*)(w2h + o) = bfu(h);
            *(unsigned short*)(w2l + o) = bfu(l);
        }
    }
    if (tid < H2) { sm[OFF_B2 + tid] = b2[tid]; sm[OFF_WF + tid] = Wf[tid]; }

    // ---- bias c: 3-way i-split over 240 threads (partials alias AW region) ----
    if (tid < 240) {
        const int blk = tid / 80;
        const int jj  = tid - blk * 80;
        const int i0  = blk * 21;
        const int i1  = (blk == 2) ? 64 : i0 + 21;
        float acc = (blk == 0) ? b1[jj] : 0.0f;
        for (int i = i0; i < i1; i++)
            acc += sm[OFF_QQ + i] * (W1[i * H1 + jj] + W1[(128 + i) * H1 + jj]);
        sm[OFF_AW + tid] = acc;
    }
    __syncthreads();
    if (tid < H1)
        sm[OFF_C + tid] = sm[OFF_AW + tid] + sm[OFF_AW + tid + 80] + sm[OFF_AW + tid + 160];
    __syncthreads();

    // ---- fused: per-warp A convert -> GEMM1 (HMMA) -> relu -> GEMM2 (HMMA) -> scores ----
    #pragma unroll 1
    for (int pass = 0; pass < 2; pass++) {
        const int tile = wid + pass * 8;
        if (tile >= 13) break;
        const int m0 = tile * 16;

        // per-warp convert of this tile's 16 rows into AW[wid]
        {
            char* aw = (char*)sm + (size_t)wid * AWBYTES;
            #pragma unroll
            for (int r = 0; r < 8; r++) {
                int idx = lid + r * 32;
                int t  = idx >> 4;
                int ch = idx & 15;
                int row = m0 + t;
                uint2 hv = make_uint2(0u, 0u), lv = make_uint2(0u, 0u);
                if (row < TT) {
                    float4 kv = *(const float4*)(kin + ((size_t)b * TT + row) * DD + ch * 4);
                    u32 h0, l0, h1, l1;
                    split2(kv.x, kv.y, h0, l0);
                    split2(kv.z, kv.w, h1, l1);
                    hv = make_uint2(h0, h1);
                    lv = make_uint2(l0, l1);
                }
                size_t o = (size_t)t * ASTRB + (size_t)ch * 8;
                *(uint2*)(aw + o) = hv;
                *(uint2*)(aw + 2304 + o) = lv;
            }
            __syncwarp();
        }

        const u32 aRowH = smb + wid * AWBYTES + (lid & 15) * ASTRB + (lid >> 4) * 16;
        const u32 aRowL = aRowH + 2304;
        const u32 bRowH = smb + OFF_BH * 4 + (lid & 15) * BSTRB;
        const u32 bRowL = smb + OFF_BL * 4 + (lid & 15) * BSTRB;

        float acc[10][4];
        #pragma unroll
        for (int n = 0; n < 10; n++) {
            acc[n][0] = 0.f; acc[n][1] = 0.f; acc[n][2] = 0.f; acc[n][3] = 0.f;
        }
        #pragma unroll
        for (int k = 0; k < 4; k++) {
            u32 ah0, ah1, ah2, ah3, al0, al1, al2, al3;
            ldmA(ah0, ah1, ah2, ah3, aRowH + k * 32);
            ldmA(al0, al1, al2, al3, aRowL + k * 32);
            #pragma unroll
            for (int n = 0; n < 10; n++) {
                u32 bh0, bh1, bl0, bl1;
                ldmB(bh0, bh1, bRowH + k * 16 * BSTRB + n * 16);
                ldmB(bl0, bl1, bRowL + k * 16 * BSTRB + n * 16);
                mma_bf16(acc[n], ah0, ah1, ah2, ah3, bh0, bh1);
                mma_bf16(acc[n], al0, al1, al2, al3, bh0, bh1);
                mma_bf16(acc[n], ah0, ah1, ah2, ah3, bl0, bl1);
            }
        }

        // bias + relu, in-register split to GEMM2 A-frags
        u32 fh[5][4], fl[5][4];
        {
            const int cc = (lid & 3) * 2;
            #pragma unroll
            for (int n = 0; n < 10; n++) {
                const float c0 = sm[OFF_C + n * 8 + cc];
                const float c1 = sm[OFF_C + n * 8 + cc + 1];
                float x0 = fmaxf(acc[n][0] + c0, 0.f);
                float x1 = fmaxf(acc[n][1] + c1, 0.f);
                float x2 = fmaxf(acc[n][2] + c0, 0.f);
                float x3 = fmaxf(acc[n][3] + c1, 0.f);
                const int kk = n >> 1;
                const int hi2 = (n & 1) * 2;
                split2(x0, x1, fh[kk][hi2],     fl[kk][hi2]);
                split2(x2, x3, fh[kk][hi2 + 1], fl[kk][hi2 + 1]);
            }
        }

        // GEMM2
        float acc2[5][4];
        {
            const int cc = (lid & 3) * 2;
            #pragma unroll
            for (int n2 = 0; n2 < 5; n2++) {
                const float bb0 = sm[OFF_B2 + n2 * 8 + cc];
                const float bb1 = sm[OFF_B2 + n2 * 8 + cc + 1];
                acc2[n2][0] = bb0; acc2[n2][1] = bb1;
                acc2[n2][2] = bb0; acc2[n2][3] = bb1;
            }
        }
        {
            const int nrow = (lid >> 2);
            const int kw   = (lid & 3);
            #pragma unroll
            for (int kk = 0; kk < 5; kk++) {
                #pragma unroll
                for (int n2 = 0; n2 < 5; n2++) {
                    const u32 base = (u32)(((n2 * 8 + nrow) * W2S + kk * 8 + kw) * 4);
                    u32 bh0 = *(const u32*)((char*)sm + (size_t)OFF_W2H * 4 + base);
                    u32 bh1 = *(const u32*)((char*)sm + (size_t)OFF_W2H * 4 + base + 16);
                    u32 bl0 = *(const u32*)((char*)sm + (size_t)OFF_W2L * 4 + base);
                    u32 bl1 = *(const u32*)((char*)sm + (size_t)OFF_W2L * 4 + base + 16);
                    mma_bf16(acc2[n2], fh[kk][0], fh[kk][1], fh[kk][2], fh[kk][3], bh0, bh1);
                    mma_bf16(acc2[n2], fl[kk][0], fl[kk][1], fl[kk][2], fl[kk][3], bh0, bh1);
                    mma_bf16(acc2[n2], fh[kk][0], fh[kk][1], fh[kk][2], fh[kk][3], bl0, bl1);
                }
            }
        }

        // scores: relu(acc2) . Wf, quad reduce
        {
            const int cc = (lid & 3) * 2;
            float s0 = 0.f, s1 = 0.f;
            #pragma unroll
            for (int n2 = 0; n2 < 5; n2++) {
                const float w0 = sm[OFF_WF + n2 * 8 + cc];
                const float w1 = sm[OFF_WF + n2 * 8 + cc + 1];
                s0 = fmaf(fmaxf(acc2[n2][0], 0.f), w0, s0);
                s0 = fmaf(fmaxf(acc2[n2][1], 0.f), w1, s0);
                s1 = fmaf(fmaxf(acc2[n2][2], 0.f), w0, s1);
                s1 = fmaf(fmaxf(acc2[n2][3], 0.f), w1, s1);
            }
            s0 += __shfl_xor_sync(0xffffffffu, s0, 1);
            s0 += __shfl_xor_sync(0xffffffffu, s0, 2);
            s1 += __shfl_xor_sync(0xffffffffu, s1, 1);
            s1 += __shfl_xor_sync(0xffffffffu, s1, 2);
            if ((lid & 3) == 0) {
                const int r0 = m0 + (lid >> 2);
                if (r0 < TT)     sm[OFF_SC + r0] = s0;
                if (r0 + 8 < TT) sm[OFF_SC + r0 + 8] = s1;
            }
        }
    }
    __syncthreads();

    // ---- bias + mask ----
    if (tid < TT) {
        float s = sm[OFF_SC + tid] + bf[0];
        if (mask[(size_t)b * TT + tid] == 0) s = NEG_BIG_F;
        sm[OFF_SC + tid] = s;
    }
    __syncthreads();

    // ---- softmax over T ----
    float mval = (tid < TT) ? sm[OFF_SC + tid] : -3.0e38f;
    #pragma unroll
    for (int o = 16; o; o >>= 1)
        mval = fmaxf(mval, __shfl_xor_sync(0xffffffffu, mval, o));
    if (lid == 0) sm[OFF_RED + wid] = mval;
    __syncthreads();
    if (tid == 0) {
        float m = sm[OFF_RED];
        #pragma unroll
        for (int w = 1; w < 8; w++) m = fmaxf(m, sm[OFF_RED + w]);
        sm[OFF_MX] = m;
    }
    __syncthreads();
    const float mx = sm[OFF_MX];
    float e = (tid < TT) ? __expf(sm[OFF_SC + tid] - mx) : 0.0f;
    if (tid < TT) sm[OFF_SC + tid] = e;
    float sval = e;
    #pragma unroll
    for (int o = 16; o; o >>= 1)
        sval += __shfl_xor_sync(0xffffffffu, sval, o);
    if (lid == 0) sm[OFF_RED + wid] = sval;
    __syncthreads();
    if (tid == 0) {
        float smv = 0.0f;
        #pragma unroll
        for (int w = 0; w < 8; w++) smv += sm[OFF_RED + w];
        sm[OFF_MX + 1] = 1.0f / smv;
    }
    __syncthreads();

    // ---- out = attn @ V (partials alias AW region) ----
    const float inv = sm[OFF_MX + 1];
    const int dd = tid & 63;
    const int p  = tid >> 6;
    const float* vb = v + (size_t)b * TT * DD;
    const float* scp = sm + OFF_SC;
    float a0 = 0.f, a1 = 0.f;
    const int t0 = p * 50;
    #pragma unroll 5
    for (int t = t0; t < t0 + 50; t += 2) {
        a0 = fmaf(scp[t],     vb[(size_t)t * DD + dd],       a0);
        a1 = fmaf(scp[t + 1], vb[(size_t)(t + 1) * DD + dd], a1);
    }
    sm[OFF_AW + tid] = a0 + a1;
    __syncthreads();
    if (tid < DD) {
        float r = sm[OFF_AW + tid] + sm[OFF_AW + tid + 64]
                + sm[OFF_AW + tid + 128] + sm[OFF_AW + tid + 192];
        out[(size_t)b * DD + tid] = r * inv;
    }
}

extern "C" void kernel_launch(void* const* d_in, const int* in_sizes, int n_in,
                              void* d_out, int out_size)
{
    const float* q    = (const float*)d_in[0];
    const float* k    = (const float*)d_in[1];
    const float* v    = (const float*)d_in[2];
    const int*   mask = (const int*)  d_in[3];
    const float* W1   = (const float*)d_in[4];
    const float* b1   = (const float*)d_in[5];
    const float* W2   = (const float*)d_in[6];
    const float* b2   = (const float*)d_in[7];
    const float* Wf   = (const float*)d_in[8];
    const float* bf   = (const float*)d_in[9];
    float* out = (float*)d_out;

    const int smem_bytes = SMEM_FLOATS * (int)sizeof(float);
    cudaFuncSetAttribute(din_attn_kernel,
                         cudaFuncAttributeMaxDynamicSharedMemorySize, smem_bytes);
    din_attn_kernel<<<BB, 256, smem_bytes>>>(q, k, v, mask, W1, b1, W2, b2, Wf, bf, out);
}

// round 13
// speedup vs baseline: 2.7082x; 1.4162x over previous
#include <cuda_runtime.h>
#include <cuda_bf16.h>
#include <math.h>

#define BB 4096
#define TT 200
#define DD 64
#define H1 80
#define H2 40
#define NEG_BIG_F (-4294967295.0f)
#define ASTRB 144   // per-warp A rows: 72 bf16 (9x16B, conflict-free ldmatrix)
#define BSTRB 176   // B rows: 88 bf16 (11x16B, conflict-free ldmatrix)
#define W2S 44      // W2^T row stride in floats (176B)
#define AWBYTES 4608  // per-warp A buffer: 16*144 (hi) + 16*144 (lo)
#define NTHR 416      // 13 warps = 13 m16 tiles

typedef unsigned long long u64;
typedef unsigned int u32;

__device__ __forceinline__ u32 smem_u32(const void* p) {
    u32 a; asm("{ .reg .u64 t; cvta.to.shared.u64 t, %1; cvt.u32.u64 %0, t; }" : "=r"(a) : "l"(p));
    return a;
}
__device__ __forceinline__ void ldmA(u32& a0, u32& a1, u32& a2, u32& a3, u32 addr) {
    asm volatile("ldmatrix.sync.aligned.m8n8.x4.shared.b16 {%0,%1,%2,%3}, [%4];"
                 : "=r"(a0), "=r"(a1), "=r"(a2), "=r"(a3) : "r"(addr));
}
__device__ __forceinline__ void ldmB(u32& b0, u32& b1, u32 addr) {
    asm volatile("ldmatrix.sync.aligned.m8n8.x2.trans.shared.b16 {%0,%1}, [%2];"
                 : "=r"(b0), "=r"(b1) : "r"(addr));
}
__device__ __forceinline__ void mma_bf16(float* d, u32 a0, u32 a1, u32 a2, u32 a3, u32 b0, u32 b1) {
    asm volatile("mma.sync.aligned.m16n8k16.row.col.f32.bf16.bf16.f32 "
                 "{%0,%1,%2,%3}, {%4,%5,%6,%7}, {%8,%9}, {%0,%1,%2,%3};"
                 : "+f"(d[0]), "+f"(d[1]), "+f"(d[2]), "+f"(d[3])
                 : "r"(a0), "r"(a1), "r"(a2), "r"(a3), "r"(b0), "r"(b1));
}
__device__ __forceinline__ unsigned short bfu(__nv_bfloat16 h) { return __bfloat16_as_ushort(h); }

__device__ __forceinline__ void split2(float x0, float x1, u32& hi, u32& lo) {
    __nv_bfloat16 h0 = __float2bfloat16_rn(x0);
    __nv_bfloat16 h1 = __float2bfloat16_rn(x1);
    __nv_bfloat16 l0 = __float2bfloat16_rn(x0 - __bfloat162float(h0));
    __nv_bfloat16 l1 = __float2bfloat16_rn(x1 - __bfloat162float(h1));
    hi = (u32)bfu(h0) | ((u32)bfu(h1) << 16);
    lo = (u32)bfu(l0) | ((u32)bfu(l1) << 16);
}

// ---------------- smem layout (float offsets) ----------------
#define OFF_AW   0            // 13 warps x 4608B = 59904B (aliases c-partials, AV partials)
#define OFF_BH   14976
#define OFF_BL   17792
#define OFF_W2H  20608
#define OFF_W2L  22368
#define OFF_C    24128        // [80]
#define OFF_B2   24208        // [40]
#define OFF_WF   24248        // [40]
#define OFF_QQ   24288        // [64]
#define OFF_SC   24352        // [208]
#define OFF_RED  24560        // [16]
#define OFF_MX   24576        // [2]
#define SMEM_FLOATS 24578

__global__ __launch_bounds__(NTHR, 2)
void din_attn_kernel(const float* __restrict__ q, const float* __restrict__ kin,
                     const float* __restrict__ v, const int* __restrict__ mask,
                     const float* __restrict__ W1, const float* __restrict__ b1,
                     const float* __restrict__ W2, const float* __restrict__ b2,
                     const float* __restrict__ Wf, const float* __restrict__ bf,
                     float* __restrict__ out)
{
    extern __shared__ float sm[];
    const int tid = threadIdx.x;
    const int wid = tid >> 5;
    const int lid = tid & 31;
    const int b   = blockIdx.x;
    const u32 smb = smem_u32(sm);

    if (tid < DD) sm[OFF_QQ + tid] = q[b * DD + tid];
    __syncthreads();

    // ---- fold W1 -> B (k x n) bf16 hi/lo ----
    {
        char* bhp = (char*)sm + (size_t)OFF_BH * 4;
        char* blp = (char*)sm + (size_t)OFF_BL * 4;
        for (int idx = tid; idx < DD * H1; idx += NTHR) {
            int i = idx / H1;
            int j = idx - i * H1;
            float w = W1[(64 + i) * H1 + j] - W1[(128 + i) * H1 + j]
                    + sm[OFF_QQ + i] * W1[(192 + i) * H1 + j];
            __nv_bfloat16 h = __float2bfloat16_rn(w);
            __nv_bfloat16 l = __float2bfloat16_rn(w - __bfloat162float(h));
            size_t o = (size_t)i * BSTRB + (size_t)j * 2;
            *(unsigned short*)(bhp + o) = bfu(h);
            *(unsigned short*)(blp + o) = bfu(l);
        }
    }

    // ---- W2^T bf16 hi/lo ----
    {
        char* w2h = (char*)sm + (size_t)OFF_W2H * 4;
        char* w2l = (char*)sm + (size_t)OFF_W2L * 4;
        for (int idx = tid; idx < H1 * H2; idx += NTHR) {
            int j = idx / H2;
            int g = idx - j * H2;
            float w = W2[idx];
            __nv_bfloat16 h = __float2bfloat16_rn(w);
            __nv_bfloat16 l = __float2bfloat16_rn(w - __bfloat162float(h));
            size_t o = (size_t)g * (W2S * 4) + (size_t)j * 2;
            *(unsigned short*)(w2h + o) = bfu(h);
            *(unsigned short*)(w2l + o) = bfu(l);
        }
    }
    if (tid < H2) { sm[OFF_B2 + tid] = b2[tid]; sm[OFF_WF + tid] = Wf[tid]; }

    // ---- bias c: 3-way i-split over 240 threads (partials alias AW region) ----
    if (tid < 240) {
        const int blk = tid / 80;
        const int jj  = tid - blk * 80;
        const int i0  = blk * 21;
        const int i1  = (blk == 2) ? 64 : i0 + 21;
        float acc = (blk == 0) ? b1[jj] : 0.0f;
        for (int i = i0; i < i1; i++)
            acc += sm[OFF_QQ + i] * (W1[i * H1 + jj] + W1[(128 + i) * H1 + jj]);
        sm[OFF_AW + tid] = acc;
    }
    __syncthreads();
    if (tid < H1)
        sm[OFF_C + tid] = sm[OFF_AW + tid] + sm[OFF_AW + tid + 80] + sm[OFF_AW + tid + 160];
    __syncthreads();

    // ---- fused: per-warp A convert -> GEMM1 (HMMA) -> relu -> GEMM2 (HMMA) -> scores ----
    // 13 warps, 13 tiles: warp w owns tile w. Single balanced pass.
    {
        const int m0 = wid * 16;

        // per-warp convert of this tile's 16 rows into AW[wid]
        {
            char* aw = (char*)sm + (size_t)wid * AWBYTES;
            #pragma unroll
            for (int r = 0; r < 8; r++) {
                int idx = lid + r * 32;
                int t  = idx >> 4;
                int ch = idx & 15;
                int row = m0 + t;
                uint2 hv = make_uint2(0u, 0u), lv = make_uint2(0u, 0u);
                if (row < TT) {
                    float4 kv = *(const float4*)(kin + ((size_t)b * TT + row) * DD + ch * 4);
                    u32 h0, l0, h1, l1;
                    split2(kv.x, kv.y, h0, l0);
                    split2(kv.z, kv.w, h1, l1);
                    hv = make_uint2(h0, h1);
                    lv = make_uint2(l0, l1);
                }
                size_t o = (size_t)t * ASTRB + (size_t)ch * 8;
                *(uint2*)(aw + o) = hv;
                *(uint2*)(aw + 2304 + o) = lv;
            }
            __syncwarp();
        }

        const u32 aRowH = smb + wid * AWBYTES + (lid & 15) * ASTRB + (lid >> 4) * 16;
        const u32 aRowL = aRowH + 2304;
        const u32 bRowH = smb + OFF_BH * 4 + (lid & 15) * BSTRB;
        const u32 bRowL = smb + OFF_BL * 4 + (lid & 15) * BSTRB;

        float acc[10][4];
        #pragma unroll
        for (int n = 0; n < 10; n++) {
            acc[n][0] = 0.f; acc[n][1] = 0.f; acc[n][2] = 0.f; acc[n][3] = 0.f;
        }
        #pragma unroll
        for (int k = 0; k < 4; k++) {
            u32 ah0, ah1, ah2, ah3, al0, al1, al2, al3;
            ldmA(ah0, ah1, ah2, ah3, aRowH + k * 32);
            ldmA(al0, al1, al2, al3, aRowL + k * 32);
            #pragma unroll
            for (int n = 0; n < 10; n++) {
                u32 bh0, bh1, bl0, bl1;
                ldmB(bh0, bh1, bRowH + k * 16 * BSTRB + n * 16);
                ldmB(bl0, bl1, bRowL + k * 16 * BSTRB + n * 16);
                mma_bf16(acc[n], ah0, ah1, ah2, ah3, bh0, bh1);
                mma_bf16(acc[n], al0, al1, al2, al3, bh0, bh1);
                mma_bf16(acc[n], ah0, ah1, ah2, ah3, bl0, bl1);
            }
        }

        // bias + relu, in-register split to GEMM2 A-frags
        u32 fh[5][4], fl[5][4];
        {
            const int cc = (lid & 3) * 2;
            #pragma unroll
            for (int n = 0; n < 10; n++) {
                const float c0 = sm[OFF_C + n * 8 + cc];
                const float c1 = sm[OFF_C + n * 8 + cc + 1];
                float x0 = fmaxf(acc[n][0] + c0, 0.f);
                float x1 = fmaxf(acc[n][1] + c1, 0.f);
                float x2 = fmaxf(acc[n][2] + c0, 0.f);
                float x3 = fmaxf(acc[n][3] + c1, 0.f);
                const int kk = n >> 1;
                const int hi2 = (n & 1) * 2;
                split2(x0, x1, fh[kk][hi2],     fl[kk][hi2]);
                split2(x2, x3, fh[kk][hi2 + 1], fl[kk][hi2 + 1]);
            }
        }

        // GEMM2
        float acc2[5][4];
        {
            const int cc = (lid & 3) * 2;
            #pragma unroll
            for (int n2 = 0; n2 < 5; n2++) {
                const float bb0 = sm[OFF_B2 + n2 * 8 + cc];
                const float bb1 = sm[OFF_B2 + n2 * 8 + cc + 1];
                acc2[n2][0] = bb0; acc2[n2][1] = bb1;
                acc2[n2][2] = bb0; acc2[n2][3] = bb1;
            }
        }
        {
            const int nrow = (lid >> 2);
            const int kw   = (lid & 3);
            #pragma unroll
            for (int kk = 0; kk < 5; kk++) {
                #pragma unroll
                for (int n2 = 0; n2 < 5; n2++) {
                    const u32 base = (u32)(((n2 * 8 + nrow) * W2S + kk * 8 + kw) * 4);
                    u32 bh0 = *(const u32*)((char*)sm + (size_t)OFF_W2H * 4 + base);
                    u32 bh1 = *(const u32*)((char*)sm + (size_t)OFF_W2H * 4 + base + 16);
                    u32 bl0 = *(const u32*)((char*)sm + (size_t)OFF_W2L * 4 + base);
                    u32 bl1 = *(const u32*)((char*)sm + (size_t)OFF_W2L * 4 + base + 16);
                    mma_bf16(acc2[n2], fh[kk][0], fh[kk][1], fh[kk][2], fh[kk][3], bh0, bh1);
                    mma_bf16(acc2[n2], fl[kk][0], fl[kk][1], fl[kk][2], fl[kk][3], bh0, bh1);
                    mma_bf16(acc2[n2], fh[kk][0], fh[kk][1], fh[kk][2], fh[kk][3], bl0, bl1);
                }
            }
        }

        // scores: relu(acc2) . Wf, quad reduce
        {
            const int cc = (lid & 3) * 2;
            float s0 = 0.f, s1 = 0.f;
            #pragma unroll
            for (int n2 = 0; n2 < 5; n2++) {
                const float w0 = sm[OFF_WF + n2 * 8 + cc];
                const float w1 = sm[OFF_WF + n2 * 8 + cc + 1];
                s0 = fmaf(fmaxf(acc2[n2][0], 0.f), w0, s0);
                s0 = fmaf(fmaxf(acc2[n2][1], 0.f), w1, s0);
                s1 = fmaf(fmaxf(acc2[n2][2], 0.f), w0, s1);
                s1 = fmaf(fmaxf(acc2[n2][3], 0.f), w1, s1);
            }
            s0 += __shfl_xor_sync(0xffffffffu, s0, 1);
            s0 += __shfl_xor_sync(0xffffffffu, s0, 2);
            s1 += __shfl_xor_sync(0xffffffffu, s1, 1);
            s1 += __shfl_xor_sync(0xffffffffu, s1, 2);
            if ((lid & 3) == 0) {
                const int r0 = m0 + (lid >> 2);
                if (r0 < TT)     sm[OFF_SC + r0] = s0;
                if (r0 + 8 < TT) sm[OFF_SC + r0 + 8] = s1;
            }
        }
    }
    __syncthreads();

    // ---- bias + mask ----
    if (tid < TT) {
        float s = sm[OFF_SC + tid] + bf[0];
        if (mask[(size_t)b * TT + tid] == 0) s = NEG_BIG_F;
        sm[OFF_SC + tid] = s;
    }
    __syncthreads();

    // ---- softmax over T (13 warps) ----
    float mval = (tid < TT) ? sm[OFF_SC + tid] : -3.0e38f;
    #pragma unroll
    for (int o = 16; o; o >>= 1)
        mval = fmaxf(mval, __shfl_xor_sync(0xffffffffu, mval, o));
    if (lid == 0) sm[OFF_RED + wid] = mval;
    __syncthreads();
    if (tid == 0) {
        float m = sm[OFF_RED];
        #pragma unroll
        for (int w = 1; w < 13; w++) m = fmaxf(m, sm[OFF_RED + w]);
        sm[OFF_MX] = m;
    }
    __syncthreads();
    const float mx = sm[OFF_MX];
    float e = (tid < TT) ? __expf(sm[OFF_SC + tid] - mx) : 0.0f;
    if (tid < TT) sm[OFF_SC + tid] = e;
    float sval = e;
    #pragma unroll
    for (int o = 16; o; o >>= 1)
        sval += __shfl_xor_sync(0xffffffffu, sval, o);
    if (lid == 0) sm[OFF_RED + wid] = sval;
    __syncthreads();
    if (tid == 0) {
        float smv = 0.0f;
        #pragma unroll
        for (int w = 0; w < 13; w++) smv += sm[OFF_RED + w];
        sm[OFF_MX + 1] = 1.0f / smv;
    }
    __syncthreads();

    // ---- out = attn @ V (6 token-groups over 384 threads; partials alias AW) ----
    const float inv = sm[OFF_MX + 1];
    if (tid < 384) {
        const int g  = tid >> 6;
        const int dd = tid & 63;
        const int start = g * 33 + (g < 2 ? g : 2);
        const int cnt   = (g < 2) ? 34 : 33;
        const float* vb = v + (size_t)b * TT * DD;
        const float* scp = sm + OFF_SC;
        float a0 = 0.f, a1 = 0.f;
        int t = start;
        for (; t + 1 < start + cnt; t += 2) {
            a0 = fmaf(scp[t],     vb[(size_t)t * DD + dd],       a0);
            a1 = fmaf(scp[t + 1], vb[(size_t)(t + 1) * DD + dd], a1);
        }
        if (t < start + cnt)
            a0 = fmaf(scp[t], vb[(size_t)t * DD + dd], a0);
        sm[OFF_AW + tid] = a0 + a1;
    }
    __syncthreads();
    if (tid < DD) {
        float r = 0.f;
        #pragma unroll
        for (int g = 0; g < 6; g++) r += sm[OFF_AW + tid + 64 * g];
        out[(size_t)b * DD + tid] = r * inv;
    }
}

extern "C" void kernel_launch(void* const* d_in, const int* in_sizes, int n_in,
                              void* d_out, int out_size)
{
    const float* q    = (const float*)d_in[0];
    const float* k    = (const float*)d_in[1];
    const float* v    = (const float*)d_in[2];
    const int*   mask = (const int*)  d_in[3];
    const float* W1   = (const float*)d_in[4];
    const float* b1   = (const float*)d_in[5];
    const float* W2   = (const float*)d_in[6];
    const float* b2   = (const float*)d_in[7];
    const float* Wf   = (const float*)d_in[8];
    const float* bf   = (const float*)d_in[9];
    float* out = (float*)d_out;

    const int smem_bytes = SMEM_FLOATS * (int)sizeof(float);
    cudaFuncSetAttribute(din_attn_kernel,
                         cudaFuncAttributeMaxDynamicSharedMemorySize, smem_bytes);
    din_attn_kernel<<<BB, NTHR, smem_bytes>>>(q, k, v, mask, W1, b1, W2, b2, Wf, bf, out);
}